// round 17
// baseline (speedup 1.0000x reference)
#include <cuda_runtime.h>
#include <cuda_fp16.h>
#include <mma.h>
#include <math.h>
#include <cstdint>

using namespace nvcuda;

#define NTOK 4096
#define DDIM 1024
#define HDIM 4096
#define ODIM 1024
#define NEXP 8
#define NPAIR 8192

#define BM 128
#define BN 256
#define BK 64
#define ALD 72      // A smem row stride (halfs)
#define BLD 264     // B smem row stride (halfs)
#define CLD 264     // C smem row stride (floats)

#define A_STAGE 18432             // 128*72*2
#define B_STAGE 33792             // 64*264*2
#define STG (A_STAGE + B_STAGE)   // 52224
#define OFF_B A_STAGE
#define NSTAGE 3
#define SMEM_GEMM (NSTAGE * STG)  // 156672 (C tile 128*264*4=135168 aliases)
#define RLD 1028                  // router smem row stride (floats)
#define SMEM_ROUTER (16 * RLD * 4)
#define W4 (NEXP * DDIM * HDIM / 4)   // float4 count per weight tensor: 8388608
#define NCONV2 256                    // W2 conv blocks appended to gemm1 grid

__device__ __forceinline__ uint32_t smem_u32(const void* p) {
    uint32_t a;
    asm("{ .reg .u64 t; cvta.to.shared.u64 t, %1; cvt.u32.u64 %0, t; }" : "=r"(a) : "l"(p));
    return a;
}
#define CP_ASYNC16(dst, src, sz) \
    asm volatile("cp.async.cg.shared.global [%0], [%1], 16, %2;" \
                 :: "r"(dst), "l"(src), "r"(sz))
#define CP_COMMIT() asm volatile("cp.async.commit_group;")
#define CP_WAIT0()  asm volatile("cp.async.wait_group 0;")
#define CP_WAIT1()  asm volatile("cp.async.wait_group 1;")

// ---------------- scratch (device globals) ----------------
__device__ int   g_cnt[NEXP];
__device__ int   g_tok[NEXP * NTOK];
// per-token routing record: for token t, slots 2t / 2t+1
__device__ int   g_ti[2 * NTOK];     // expert index
__device__ int   g_tp[2 * NTOK];     // position within expert list
__device__ float g_tg[2 * NTOK];     // gate
__device__ __half g_xh[NTOK * DDIM];                 // fp16(x)
__device__ __half g_w1h[NEXP * DDIM * HDIM];         // fp16(W1)
__device__ __half g_w2h[NEXP * HDIM * ODIM];         // fp16(W2)
__device__ __half g_h[(size_t)NPAIR * HDIM];         // fp16(h)
__device__ float  g_ct[(size_t)NPAIR * ODIM];        // gemm2 contributions

// ---------------- router + fused conversions (x and a W1 stripe per block) ----------------
__global__ void router_kernel(const float* __restrict__ x,
                              const float* __restrict__ noise,
                              const float* __restrict__ Wg,
                              const float* __restrict__ bg,
                              const float* __restrict__ Wn,
                              const float* __restrict__ bn,
                              const float4* __restrict__ W1) {
    extern __shared__ float Ws[];  // [16][RLD] rows: 0..7 Wg cols, 8..15 Wn cols
    int tid = threadIdx.x;
    for (int idx = tid; idx < DDIM * NEXP; idx += blockDim.x) {
        int k = idx >> 3, o = idx & 7;
        Ws[o * RLD + k]       = Wg[idx];
        Ws[(8 + o) * RLD + k] = Wn[idx];
    }
    __syncthreads();
    int warp = tid >> 5, lane = tid & 31;
    int o = lane & 15, half = lane >> 4;
    int t = blockIdx.x * 16 + warp * 2 + half;

    const float4* xr = (const float4*)(x + (size_t)t * DDIM);
    const float4* wr = (const float4*)(Ws + o * RLD);
    float acc = 0.f;
#pragma unroll 8
    for (int k = 0; k < 256; ++k) {
        float4 xv = xr[k];
        float4 wv = wr[k];
        acc += xv.x * wv.x + xv.y * wv.y + xv.z * wv.z + xv.w * wv.w;
    }
    float nl_other = __shfl_sync(0xffffffffu, acc, (lane + 8) & 31);
    float noisy = -3.4e38f;
    if (o < 8) {
        float lg = acc + bg[o];
        float nl = nl_other + bn[o];
        float sp = nl > 20.f ? nl : log1pf(expf(nl));
        noisy = lg + noise[(size_t)t * 8 + o] * sp;
    }
    float v[8];
#pragma unroll
    for (int oo = 0; oo < 8; ++oo)
        v[oo] = __shfl_sync(0xffffffffu, noisy, (half << 4) + oo);
    if (o == 0) {
        int i1 = 0; float v1 = v[0];
#pragma unroll
        for (int oo = 1; oo < 8; ++oo) if (v[oo] > v1) { v1 = v[oo]; i1 = oo; }
        int i2 = 0; float v2 = -3.4e38f;
#pragma unroll
        for (int oo = 0; oo < 8; ++oo) if (oo != i1 && v[oo] > v2) { v2 = v[oo]; i2 = oo; }
        float ex = expf(v2 - v1);
        float inv = 1.f / (1.f + ex);
        float gg2 = ex * inv;
        int p1 = atomicAdd(&g_cnt[i1], 1);
        g_tok[i1 * NTOK + p1] = t;
        int p2 = atomicAdd(&g_cnt[i2], 1);
        g_tok[i2 * NTOK + p2] = t;
        g_ti[2 * t] = i1;  g_tp[2 * t] = p1;  g_tg[2 * t] = inv;
        g_ti[2 * t + 1] = i2;  g_tp[2 * t + 1] = p2;  g_tg[2 * t + 1] = gg2;
    }
    // fused fp32->fp16 conversion of this block's 16 token rows (L1/L2 hot)
    int t0 = blockIdx.x * 16;
    for (int i = tid; i < 16 * (DDIM / 4); i += blockDim.x) {
        int row = i >> 8, col = i & 255;
        float4 vx = *(const float4*)(x + (size_t)(t0 + row) * DDIM + col * 4);
        __half2* dst = (__half2*)(g_xh + (size_t)(t0 + row) * DDIM + col * 4);
        dst[0] = __halves2half2(__float2half_rn(vx.x), __float2half_rn(vx.y));
        dst[1] = __halves2half2(__float2half_rn(vx.z), __float2half_rn(vx.w));
    }
    // fused W1 fp32->fp16: each of the 256 blocks converts a 32768-float4 stripe
    {
        const int stripe = W4 / (NTOK / 16);             // 32768
        size_t j0 = (size_t)blockIdx.x * stripe;
        __half2* hi = (__half2*)g_w1h;
#pragma unroll 4
        for (int i = tid; i < stripe; i += 256) {
            size_t j = j0 + i;
            float4 vv = W1[j];
            hi[2 * j]     = __halves2half2(__float2half_rn(vv.x), __float2half_rn(vv.y));
            hi[2 * j + 1] = __halves2half2(__float2half_rn(vv.z), __float2half_rn(vv.w));
        }
    }
}

// ---------------- grouped GEMM (R8 engine, unchanged mainloop) ----------------
// SECOND=false: h = relu(gather(xh) @ W1h[e] + b1[e]) -> g_h (fp16)
//               blocks with blockIdx.y >= NEXP*32 instead convert a W2 stripe
//               (scheduled last -> they backfill gemm1's tail-wave idle SMs)
// SECOND=true : g_ct[row] = h @ W2h[e]   (plain stores; bias+gate in combine)
template <bool SECOND>
__global__ void __launch_bounds__(256, 1)
moe_gemm_kernel(const float* __restrict__ bias, const float4* __restrict__ W2) {
    constexpr int KDIM = SECOND ? HDIM : DDIM;
    constexpr int NDIM = SECOND ? ODIM : HDIM;
    constexpr int KT = KDIM / BK;
    int tid = threadIdx.x;

    if (!SECOND && blockIdx.y >= NEXP * 32) {
        // W2 fp32->fp16 stripe conversion (tail-filler blocks)
        int cid = (blockIdx.y - NEXP * 32) * gridDim.x + blockIdx.x;  // 0..NCONV2-1
        const int stripe = W4 / NCONV2;                               // 32768
        size_t j0 = (size_t)cid * stripe;
        __half2* hi = (__half2*)g_w2h;
#pragma unroll 4
        for (int i = tid; i < stripe; i += 256) {
            size_t j = j0 + i;
            float4 vv = W2[j];
            hi[2 * j]     = __halves2half2(__float2half_rn(vv.x), __float2half_rn(vv.y));
            hi[2 * j + 1] = __halves2half2(__float2half_rn(vv.z), __float2half_rn(vv.w));
        }
        return;
    }

    int e  = blockIdx.y >> 5;
    int mt = blockIdx.y & 31;
    int cnt = g_cnt[e];
    int m0 = mt * BM;
    if (m0 >= cnt) return;
    int off = 0;
#pragma unroll
    for (int q = 0; q < NEXP; ++q) off += (q < e) ? g_cnt[q] : 0;
    int n0 = blockIdx.x * BN;
    int w = tid >> 5;
    int wm = (w & 1) * 64, wn = (w >> 1) * 64;

    extern __shared__ __align__(128) char raw[];
    uint32_t sbase = smem_u32(raw);

    const __half* Asrc = SECOND ? g_h : g_xh;
    const __half* Bsrc = SECOND ? g_w2h : g_w1h;

    // A: chunk id = tid + 256*i (i<4): row = id>>3, c8 = id&7 (8 halfs = 16B)
    size_t asrc[4]; uint32_t asz[4]; uint32_t adst[4];
#pragma unroll
    for (int i = 0; i < 4; ++i) {
        int id = tid + 256 * i;
        int row = id >> 3, c8 = id & 7;
        int pos = m0 + row;
        bool aval = pos < cnt;
        asz[i] = aval ? 16u : 0u;
        if (SECOND) {
            asrc[i] = (size_t)(off + (aval ? pos : 0)) * HDIM + c8 * 8;
        } else {
            int token = aval ? g_tok[e * NTOK + pos] : 0;
            asrc[i] = (size_t)token * DDIM + c8 * 8;
        }
        adst[i] = sbase + row * (ALD * 2) + c8 * 16;
    }
    // B: chunk id = tid + 256*i (i<8): row = id>>5, c16 = id&31
    size_t bsrc[8]; uint32_t bdst[8];
#pragma unroll
    for (int i = 0; i < 8; ++i) {
        int id = tid + 256 * i;
        int row = id >> 5, c16 = id & 31;
        bsrc[i] = (size_t)e * KDIM * NDIM + (size_t)row * NDIM + n0 + c16 * 8;
        bdst[i] = sbase + OFF_B + row * (BLD * 2) + c16 * 16;
    }

    auto fill = [&](int s, int kt) {
        int ko = kt * BK;
        uint32_t sb = s * STG;
#pragma unroll
        for (int i = 0; i < 4; ++i)
            CP_ASYNC16(adst[i] + sb, (const char*)(Asrc + asrc[i] + ko), asz[i]);
        size_t kofs = (size_t)ko * NDIM;
#pragma unroll
        for (int i = 0; i < 8; ++i)
            CP_ASYNC16(bdst[i] + sb, (const char*)(Bsrc + bsrc[i] + kofs), 16u);
        CP_COMMIT();
    };

    wmma::fragment<wmma::accumulator, 16, 16, 16, float> acc[4][4];
#pragma unroll
    for (int i = 0; i < 4; ++i)
#pragma unroll
        for (int j = 0; j < 4; ++j) wmma::fill_fragment(acc[i][j], 0.f);

    auto compute = [&](int s) {
        const __half* Ah = (const __half*)(raw + s * STG);
        const __half* Bh = (const __half*)(raw + s * STG + OFF_B);
#pragma unroll
        for (int kk = 0; kk < BK; kk += 16) {
            wmma::fragment<wmma::matrix_a, 16, 16, 16, __half, wmma::row_major> fa[4];
            wmma::fragment<wmma::matrix_b, 16, 16, 16, __half, wmma::row_major> fb[4];
#pragma unroll
            for (int i = 0; i < 4; ++i)
                wmma::load_matrix_sync(fa[i], Ah + (wm + 16 * i) * ALD + kk, ALD);
#pragma unroll
            for (int j = 0; j < 4; ++j)
                wmma::load_matrix_sync(fb[j], Bh + kk * BLD + wn + 16 * j, BLD);
#pragma unroll
            for (int i = 0; i < 4; ++i)
#pragma unroll
                for (int j = 0; j < 4; ++j)
                    wmma::mma_sync(acc[i][j], fa[i], fb[j], acc[i][j]);
        }
    };

    fill(0, 0);
    fill(1, 1);
#pragma unroll 1
    for (int kt = 0; kt < KT; ++kt) {
        if (KT - kt >= 2) CP_WAIT1(); else CP_WAIT0();
        __syncthreads();
        if (kt + 2 < KT) fill((kt + 2) % NSTAGE, kt + 2);
        compute(kt % NSTAGE);
    }

    // epilogue via smem C tile (aliased over stage buffers)
    __syncthreads();
    float* sC = (float*)raw;
#pragma unroll
    for (int i = 0; i < 4; ++i)
#pragma unroll
        for (int j = 0; j < 4; ++j)
            wmma::store_matrix_sync(sC + (wm + 16 * i) * CLD + wn + 16 * j, acc[i][j], CLD,
                                    wmma::mem_row_major);
    __syncthreads();

    if (!SECOND) {
        for (int q = tid; q < BM * (BN / 8); q += 256) {
            int r = q >> 5;
            int c = (q & 31) * 8;
            int pos = m0 + r;
            if (pos >= cnt) continue;
            int nb = n0 + c;
            uint4 pk;
            __half2 p[4];
#pragma unroll
            for (int u = 0; u < 4; ++u) {
                float v0 = sC[r * CLD + c + 2 * u]     + bias[e * NDIM + nb + 2 * u];
                float v1 = sC[r * CLD + c + 2 * u + 1] + bias[e * NDIM + nb + 2 * u + 1];
                p[u] = __halves2half2(__float2half_rn(fmaxf(v0, 0.f)),
                                      __float2half_rn(fmaxf(v1, 0.f)));
            }
            pk.x = *(uint32_t*)&p[0]; pk.y = *(uint32_t*)&p[1];
            pk.z = *(uint32_t*)&p[2]; pk.w = *(uint32_t*)&p[3];
            *(uint4*)(g_h + (size_t)(off + pos) * HDIM + nb) = pk;
        }
    } else {
        // plain stores of raw contributions (bias/gate applied in combine kernel)
        for (int q = tid; q < BM * (BN / 8); q += 256) {
            int r = q >> 5;
            int c = (q & 31) * 8;
            int pos = m0 + r;
            if (pos >= cnt) continue;
            int nb = n0 + c;
            float* dst = g_ct + (size_t)(off + pos) * ODIM + nb;
            float4 v0 = *(float4*)(sC + r * CLD + c);
            float4 v1 = *(float4*)(sC + r * CLD + c + 4);
            *(float4*)(dst)     = v0;
            *(float4*)(dst + 4) = v1;
        }
    }
}

// ---------------- combine: out[t] = g1*(c[r1]+b2[e1]) + g2*(c[r2]+b2[e2]) ----------------
__global__ void combine_kernel(const float* __restrict__ b2, float4* __restrict__ out) {
    int t = blockIdx.x, tid = threadIdx.x;
    __shared__ int s_r1, s_r2, s_e1, s_e2;
    __shared__ float s_g1, s_g2;
    if (tid == 0) {
        int e1 = g_ti[2 * t], e2 = g_ti[2 * t + 1];
        int off1 = 0, off2 = 0;
#pragma unroll
        for (int q = 0; q < NEXP; ++q) {
            int c = g_cnt[q];
            off1 += (q < e1) ? c : 0;
            off2 += (q < e2) ? c : 0;
        }
        s_e1 = e1; s_e2 = e2;
        s_r1 = off1 + g_tp[2 * t];
        s_r2 = off2 + g_tp[2 * t + 1];
        s_g1 = g_tg[2 * t];
        s_g2 = g_tg[2 * t + 1];
    }
    __syncthreads();
    const float4* c1 = (const float4*)(g_ct + (size_t)s_r1 * ODIM);
    const float4* c2 = (const float4*)(g_ct + (size_t)s_r2 * ODIM);
    const float4* bb1 = (const float4*)(b2 + s_e1 * ODIM);
    const float4* bb2 = (const float4*)(b2 + s_e2 * ODIM);
    float g1 = s_g1, g2 = s_g2;
    float4 a = c1[tid], b = c2[tid], x1 = bb1[tid], x2 = bb2[tid];
    float4 o;
    o.x = g1 * (a.x + x1.x) + g2 * (b.x + x2.x);
    o.y = g1 * (a.y + x1.y) + g2 * (b.y + x2.y);
    o.z = g1 * (a.z + x1.z) + g2 * (b.z + x2.z);
    o.w = g1 * (a.w + x1.w) + g2 * (b.w + x2.w);
    out[(size_t)t * (ODIM / 4) + tid] = o;
}

// ---------------- launch ----------------
extern "C" void kernel_launch(void* const* d_in, const int* in_sizes, int n_in,
                              void* d_out, int out_size) {
    const float* x     = (const float*)d_in[0];
    const float* noise = (const float*)d_in[1];
    const float* Wg    = (const float*)d_in[2];
    const float* bg    = (const float*)d_in[3];
    const float* Wn    = (const float*)d_in[4];
    const float* bn    = (const float*)d_in[5];
    const float* W1    = (const float*)d_in[6];
    const float* b1    = (const float*)d_in[7];
    const float* W2    = (const float*)d_in[8];
    const float* b2    = (const float*)d_in[9];
    (void)in_sizes; (void)n_in; (void)out_size;

    void* cnt_ptr;
    cudaGetSymbolAddress(&cnt_ptr, g_cnt);

    cudaFuncSetAttribute(router_kernel, cudaFuncAttributeMaxDynamicSharedMemorySize, SMEM_ROUTER);
    cudaFuncSetAttribute(moe_gemm_kernel<false>, cudaFuncAttributeMaxDynamicSharedMemorySize, SMEM_GEMM);
    cudaFuncSetAttribute(moe_gemm_kernel<true>,  cudaFuncAttributeMaxDynamicSharedMemorySize, SMEM_GEMM);

    // launches: 0 memset cnt, 1 router(+conv_x+conv_W1), 2 gemm1(+conv_W2 tail),
    //           3 gemm2, 4 combine
    cudaMemsetAsync(cnt_ptr, 0, NEXP * sizeof(int));

    router_kernel<<<NTOK / 16, 256, SMEM_ROUTER>>>(x, noise, Wg, bg, Wn, bn,
                                                   (const float4*)W1);

    moe_gemm_kernel<false><<<dim3(HDIM / BN, NEXP * 32 + NCONV2 / (HDIM / BN)), 256,
                             SMEM_GEMM>>>(b1, (const float4*)W2);
    moe_gemm_kernel<true> <<<dim3(ODIM / BN, NEXP * 32), 256, SMEM_GEMM>>>(nullptr, nullptr);
    combine_kernel<<<NTOK, 256>>>(b2, (float4*)d_out);
}